// round 1
// baseline (speedup 1.0000x reference)
#include <cuda_runtime.h>
#include <cstdint>
#include <math.h>

#define BM 128
#define BN 128
#define BK 32
#define BKP 36          // pad 4 -> conflict-free fragment LDS and STS.128
#define NTHREADS 256

// Scratch (allocation-free rule: __device__ globals)
__device__ float g_mid[4096 * 100];
__device__ float g_lc[(size_t)4096 * 2048];

struct GemmParams {
  int M, N, Ktot, nseg;
  const float* aptr[4];
  int ald[4];
  int kstart[5];
  const float* W; int wld;
  const float* bias1;
  const float* bias2;
  const float* addC; int addld;
  float* C; int ldc;
  int act;  // 0 none, 1 relu, 2 tanh
};

__device__ __forceinline__ uint32_t f2tf32(float x) {
  uint32_t r;
  asm("cvt.rna.tf32.f32 %0, %1;" : "=r"(r) : "f"(x));
  return r;
}

__global__ __launch_bounds__(NTHREADS, 1)
void gemm_tf32_kernel(GemmParams p) {
  extern __shared__ uint32_t smem[];
  uint32_t* Abase = smem;                     // 2 * BM * BKP
  uint32_t* Bbase = smem + 2 * BM * BKP;      // 2 * BN * BKP

  const int tid  = threadIdx.x;
  const int lane = tid & 31;
  const int warp = tid >> 5;
  const int wm   = warp >> 2;   // 0..1  -> 64-row slice
  const int wn   = warp & 3;    // 0..3  -> 32-col slice
  const int gid  = lane >> 2;
  const int tig  = lane & 3;

  const int m0 = blockIdx.y * BM;
  const int n0 = blockIdx.x * BN;

  float acc[4][4][4];
#pragma unroll
  for (int a = 0; a < 4; a++)
#pragma unroll
    for (int b = 0; b < 4; b++)
#pragma unroll
      for (int c = 0; c < 4; c++) acc[a][b][c] = 0.f;

  const int nkt = (p.Ktot + BK - 1) / BK;

  float4 ra[4], rb[4];

  auto load_tiles = [&](int k0) {
#pragma unroll
    for (int i = 0; i < 4; i++) {
      int idx = tid + i * NTHREADS;
      int row = idx >> 3;
      int c4  = (idx & 7) << 2;
      int gk  = k0 + c4;
      float4 va = make_float4(0.f, 0.f, 0.f, 0.f);
      if (gk < p.Ktot) {
        int s = 0;
#pragma unroll
        for (int j = 1; j < 4; j++)
          if (j < p.nseg && gk >= p.kstart[j]) s = j;
        va = *(const float4*)(p.aptr[s] + (size_t)(m0 + row) * p.ald[s] +
                              (gk - p.kstart[s]));
      }
      ra[i] = va;
      float4 vb = make_float4(0.f, 0.f, 0.f, 0.f);
      int n = n0 + row;
      if (gk < p.Ktot && n < p.N) {
        vb = *(const float4*)(p.W + (size_t)n * p.wld + gk);
      }
      rb[i] = vb;
    }
  };

  auto store_tiles = [&](int buf) {
    uint32_t* a = Abase + buf * BM * BKP;
    uint32_t* b = Bbase + buf * BN * BKP;
#pragma unroll
    for (int i = 0; i < 4; i++) {
      int idx = tid + i * NTHREADS;
      int row = idx >> 3;
      int c4  = (idx & 7) << 2;
      uint4 pa = make_uint4(f2tf32(ra[i].x), f2tf32(ra[i].y),
                            f2tf32(ra[i].z), f2tf32(ra[i].w));
      *(uint4*)(a + row * BKP + c4) = pa;
      uint4 pb = make_uint4(f2tf32(rb[i].x), f2tf32(rb[i].y),
                            f2tf32(rb[i].z), f2tf32(rb[i].w));
      *(uint4*)(b + row * BKP + c4) = pb;
    }
  };

  load_tiles(0);
  store_tiles(0);
  __syncthreads();

  for (int kt = 0; kt < nkt; ++kt) {
    int cur = kt & 1;
    if (kt + 1 < nkt) load_tiles((kt + 1) * BK);
    const uint32_t* a = Abase + cur * BM * BKP;
    const uint32_t* b = Bbase + cur * BN * BKP;
#pragma unroll
    for (int ks = 0; ks < BK / 8; ++ks) {
      uint32_t af[4][4], bf[4][2];
#pragma unroll
      for (int tm = 0; tm < 4; tm++) {
        int r = wm * 64 + tm * 16 + gid;
        int c = ks * 8 + tig;
        af[tm][0] = a[r * BKP + c];
        af[tm][1] = a[(r + 8) * BKP + c];
        af[tm][2] = a[r * BKP + c + 4];
        af[tm][3] = a[(r + 8) * BKP + c + 4];
      }
#pragma unroll
      for (int tn = 0; tn < 4; tn++) {
        int n = wn * 32 + tn * 8 + gid;
        int c = ks * 8 + tig;
        bf[tn][0] = b[n * BKP + c];
        bf[tn][1] = b[n * BKP + c + 4];
      }
#pragma unroll
      for (int tm = 0; tm < 4; tm++)
#pragma unroll
        for (int tn = 0; tn < 4; tn++) {
          asm volatile(
              "mma.sync.aligned.m16n8k8.row.col.f32.tf32.tf32.f32 "
              "{%0,%1,%2,%3}, {%4,%5,%6,%7}, {%8,%9}, {%0,%1,%2,%3};\n"
              : "+f"(acc[tm][tn][0]), "+f"(acc[tm][tn][1]),
                "+f"(acc[tm][tn][2]), "+f"(acc[tm][tn][3])
              : "r"(af[tm][0]), "r"(af[tm][1]), "r"(af[tm][2]), "r"(af[tm][3]),
                "r"(bf[tn][0]), "r"(bf[tn][1]));
        }
    }
    if (kt + 1 < nkt) {
      store_tiles(cur ^ 1);
      __syncthreads();
    }
  }

  // Epilogue: bias(es), optional C-addend, activation
#pragma unroll
  for (int tm = 0; tm < 4; tm++) {
#pragma unroll
    for (int tn = 0; tn < 4; tn++) {
      int row0 = m0 + wm * 64 + tm * 16 + gid;
      int col0 = n0 + wn * 32 + tn * 8 + 2 * tig;
#pragma unroll
      for (int h = 0; h < 2; ++h) {
        int r = row0 + h * 8;
#pragma unroll
        for (int q = 0; q < 2; ++q) {
          int c = col0 + q;
          if (c < p.N) {
            float v = acc[tm][tn][h * 2 + q];
            v += p.bias1[c];
            if (p.bias2) v += p.bias2[c];
            if (p.addC)  v += p.addC[(size_t)r * p.addld + c];
            if (p.act == 1)      v = fmaxf(v, 0.f);
            else if (p.act == 2) v = tanhf(v);
            p.C[(size_t)r * p.ldc + c] = v;
          }
        }
      }
    }
  }
}

static void launch_gemm(const GemmParams& p) {
  dim3 grid((p.N + BN - 1) / BN, (p.M + BM - 1) / BM);
  size_t smem = (size_t)(2 * BM * BKP + 2 * BN * BKP) * sizeof(uint32_t); // 73728
  gemm_tf32_kernel<<<grid, NTHREADS, smem>>>(p);
}

extern "C" void kernel_launch(void* const* d_in, const int* in_sizes, int n_in,
                              void* d_out, int out_size) {
  (void)in_sizes; (void)n_in; (void)out_size;
  const float* input  = (const float*)d_in[0];
  const float* hidden = (const float*)d_in[1];
  const float* prevh  = (const float*)d_in[2];
  const float* cell   = (const float*)d_in[3];
  const float* W_ch2  = (const float*)d_in[4];
  const float* b_ch2  = (const float*)d_in[5];
  const float* W_cm2  = (const float*)d_in[6];
  const float* b_cm2  = (const float*)d_in[7];
  const float* W_mo   = (const float*)d_in[8];
  const float* b_mo   = (const float*)d_in[9];
  const float* W_ci   = (const float*)d_in[10];
  const float* b_ci   = (const float*)d_in[11];
  const float* W_ch   = (const float*)d_in[12];
  const float* b_ch   = (const float*)d_in[13];
  const float* W_fc   = (const float*)d_in[14];
  const float* b_fc   = (const float*)d_in[15];
  const float* bias   = (const float*)d_in[16];
  // d_in[17] = k (static 1), unused

  float* out_p = (float*)d_out;                        // [4096,256]
  float* nh_p  = out_p + (size_t)4096 * 256;           // new_hidden [4096,2048]
  float* nc_p  = nh_p + (size_t)4096 * 2048;           // new_cell   [4096,2048]
  float* nph_p = nc_p + (size_t)4096 * 2048;           // new_prev_hidden

  float* mid_p = nullptr; float* lc_p = nullptr;
  cudaGetSymbolAddress((void**)&mid_p, g_mid);
  cudaGetSymbolAddress((void**)&lc_p, g_lc);

  cudaFuncSetAttribute(gemm_tf32_kernel,
                       cudaFuncAttributeMaxDynamicSharedMemorySize, 73728);

  // 1) new_hidden = concat @ W_ch2^T + b_ch2
  GemmParams p{};
  p.M = 4096; p.N = 2048; p.Ktot = 7168; p.nseg = 4;
  p.aptr[0] = input; p.aptr[1] = hidden; p.aptr[2] = prevh; p.aptr[3] = cell;
  p.ald[0] = 1024; p.ald[1] = 2048; p.ald[2] = 2048; p.ald[3] = 2048;
  p.kstart[0] = 0; p.kstart[1] = 1024; p.kstart[2] = 3072;
  p.kstart[3] = 5120; p.kstart[4] = 7168;
  p.W = W_ch2; p.wld = 7168; p.bias1 = b_ch2;
  p.C = nh_p; p.ldc = 2048; p.act = 0;
  launch_gemm(p);

  // 2) mid = relu(concat @ W_cm2^T + b_cm2)  (N=100)
  p.N = 100; p.W = W_cm2; p.bias1 = b_cm2; p.C = mid_p; p.ldc = 100; p.act = 1;
  launch_gemm(p);

  // 3) out = mid @ W_mo^T + b_mo  (K=100)
  GemmParams q{};
  q.M = 4096; q.N = 256; q.Ktot = 100; q.nseg = 1;
  q.aptr[0] = mid_p; q.ald[0] = 100; q.kstart[0] = 0; q.kstart[1] = 100;
  q.W = W_mo; q.wld = 100; q.bias1 = b_mo;
  q.C = out_p; q.ldc = 256; q.act = 0;
  launch_gemm(q);

  // 4) h_proj = new_hidden @ W_ch^T + b_ch  -> new_prev_hidden output region
  GemmParams r{};
  r.M = 4096; r.N = 2048; r.Ktot = 2048; r.nseg = 1;
  r.aptr[0] = nh_p; r.ald[0] = 2048; r.kstart[0] = 0; r.kstart[1] = 2048;
  r.W = W_ch; r.wld = 2048; r.bias1 = b_ch;
  r.C = nph_p; r.ldc = 2048; r.act = 0;
  launch_gemm(r);

  // 5) lc = input @ W_ci^T + b_ci + bias + h_proj
  GemmParams s{};
  s.M = 4096; s.N = 2048; s.Ktot = 1024; s.nseg = 1;
  s.aptr[0] = input; s.ald[0] = 1024; s.kstart[0] = 0; s.kstart[1] = 1024;
  s.W = W_ci; s.wld = 1024; s.bias1 = b_ci; s.bias2 = bias;
  s.addC = nph_p; s.addld = 2048;
  s.C = lc_p; s.ldc = 2048; s.act = 0;
  launch_gemm(s);

  // 6) new_cell = tanh(lc @ W_fc^T + b_fc)
  GemmParams t{};
  t.M = 4096; t.N = 2048; t.Ktot = 2048; t.nseg = 1;
  t.aptr[0] = lc_p; t.ald[0] = 2048; t.kstart[0] = 0; t.kstart[1] = 2048;
  t.W = W_fc; t.wld = 2048; t.bias1 = b_fc;
  t.C = nc_p; t.ldc = 2048; t.act = 2;
  launch_gemm(t);
}

// round 2
// speedup vs baseline: 1.7390x; 1.7390x over previous
#include <cuda_runtime.h>
#include <cstdint>
#include <math.h>

#define STAGES 4
#define NTHREADS 256
// CTA tile 256x128, BK=32, padded K-pitch 36 words
#define ASZ (256 * 36)
#define BSZ (128 * 36)
#define SMEM_BYTES ((STAGES * (ASZ + BSZ)) * 4)   // 221184

// ---------------- scratch (__device__ globals: allocation-free rule) ----------
__device__ float g_concat[(size_t)4096 * 7168];   // rounded concat
__device__ float g_Wch2[(size_t)2048 * 7168];
__device__ float g_Wcm2[(size_t)100 * 7168];
__device__ float g_Wmo[(size_t)256 * 112];        // padded ld=112, cols>=100 zero
__device__ float g_Wci[(size_t)2048 * 1024];
__device__ float g_Wch[(size_t)2048 * 2048];
__device__ float g_Wfc[(size_t)2048 * 2048];
__device__ float g_nhr[(size_t)4096 * 2048];      // rounded new_hidden
__device__ float g_lcr[(size_t)4096 * 2048];      // rounded lc
__device__ float g_midp[(size_t)8 * 4096 * 128];  // split-K partials for mid
__device__ float g_midr[(size_t)4096 * 112];      // rounded relu(mid), padded

// ---------------- helpers ----------------------------------------------------
__device__ __forceinline__ float rna(float x) {
  uint32_t r;
  asm("cvt.rna.tf32.f32 %0, %1;" : "=r"(r) : "f"(x));
  return __uint_as_float(r);
}

__device__ __forceinline__ void cpasync16(uint32_t saddr, const void* g, int sz) {
  asm volatile("cp.async.cg.shared.global [%0], [%1], 16, %2;\n"
               :: "r"(saddr), "l"(g), "r"(sz));
}
#define CP_COMMIT() asm volatile("cp.async.commit_group;\n" ::: "memory")

// ---------------- preprocessing kernels ---------------------------------------
__global__ void rna1d(float* __restrict__ dst, const float* __restrict__ src, int n4) {
  int i = blockIdx.x * blockDim.x + threadIdx.x;
  if (i < n4) {
    float4 v = ((const float4*)src)[i];
    v.x = rna(v.x); v.y = rna(v.y); v.z = rna(v.z); v.w = rna(v.w);
    ((float4*)dst)[i] = v;
  }
}

// copies rows x scols from src(ld=sld) into dst(ld=dld), rounding; cols in
// [scols, dcols) written as 0.  scols/dcols multiples of 4.
__global__ void rna2d(float* __restrict__ dst, int dld,
                      const float* __restrict__ src, int sld,
                      int rows, int scols, int dcols) {
  int dc4 = dcols >> 2;
  int total = rows * dc4;
  int i = blockIdx.x * blockDim.x + threadIdx.x;
  if (i >= total) return;
  int r = i / dc4;
  int c = (i - r * dc4) << 2;
  float4 v = make_float4(0.f, 0.f, 0.f, 0.f);
  if (c < scols) {
    v = *(const float4*)(src + (size_t)r * sld + c);
    v.x = rna(v.x); v.y = rna(v.y); v.z = rna(v.z); v.w = rna(v.w);
  }
  *(float4*)(dst + (size_t)r * dld + c) = v;
}

// mid reduce: sum 8 split-K partials + bias, relu, round -> g_midr [4096,112]
__global__ void reduce_mid(const float* __restrict__ part,
                           const float* __restrict__ bias,
                           float* __restrict__ outr) {
  int i = blockIdx.x * blockDim.x + threadIdx.x;
  if (i >= 4096 * 112) return;
  int r = i / 112, c = i - r * 112;
  float v = 0.f;
  if (c < 100) {
    float s = bias[c];
#pragma unroll
    for (int z = 0; z < 8; z++)
      s += part[(size_t)z * 4096 * 128 + (size_t)r * 128 + c];
    v = rna(fmaxf(s, 0.f));
  }
  outr[(size_t)r * 112 + c] = v;
}

// ---------------- main GEMM --------------------------------------------------
struct GP {
  int M, N, Ktot;          // Ktot = logical K for zero-fill predicate
  int lda, ldb;
  const float* A;
  const float* B;
  const float* bias1;
  const float* bias2;
  const float* addC; int addld;
  float* C1; int ldc1;     // exact output (or split-K partial base)
  float* C2; int ldc2;     // rounded output
  int act;                 // 0 none, 2 tanh (relu handled in reduce_mid)
  int nkt;                 // k-tiles handled per z-slice
  int partial;             // 1: write raw partials at C1 + z*partStride, ld 128
  long long partStride;
};

__global__ __launch_bounds__(NTHREADS, 1)
void gemm_k(GP p) {
  extern __shared__ float sm[];
  float* As = sm;
  float* Bs = sm + (size_t)STAGES * ASZ;
  uint32_t sA = (uint32_t)__cvta_generic_to_shared(As);
  uint32_t sB = (uint32_t)__cvta_generic_to_shared(Bs);

  const int tid  = threadIdx.x;
  const int lane = tid & 31;
  const int warp = tid >> 5;
  const int wm   = warp >> 1;    // 0..3 -> 64-row slice of 256
  const int wn   = warp & 1;     // 0..1 -> 64-col slice of 128
  const int gid  = lane >> 2;
  const int tig  = lane & 3;

  const int m0 = blockIdx.y * 256;
  const int n0 = blockIdx.x * 128;
  const int z  = blockIdx.z;
  const int kt0 = z * p.nkt;

  float acc[4][8][4];
#pragma unroll
  for (int a = 0; a < 4; a++)
#pragma unroll
    for (int b = 0; b < 8; b++)
#pragma unroll
      for (int c = 0; c < 4; c++) acc[a][b][c] = 0.f;

  auto issue = [&](int kti) {
    int buf = kti & (STAGES - 1);
    int k0 = (kt0 + kti) * 32;
    uint32_t da = sA + buf * (ASZ * 4);
    uint32_t db = sB + buf * (BSZ * 4);
#pragma unroll
    for (int i = 0; i < 8; i++) {
      int idx = tid + i * NTHREADS;
      int row = idx >> 3;
      int c4  = (idx & 7) << 2;
      const float* g = p.A + (size_t)(m0 + row) * p.lda + k0 + c4;
      int sz = (k0 + c4 < p.Ktot) ? 16 : 0;
      cpasync16(da + (uint32_t)(row * 36 + c4) * 4, g, sz);
    }
#pragma unroll
    for (int i = 0; i < 4; i++) {
      int idx = tid + i * NTHREADS;
      int row = idx >> 3;
      int c4  = (idx & 7) << 2;
      const float* g = p.B + (size_t)(n0 + row) * p.ldb + k0 + c4;
      int sz = ((k0 + c4 < p.Ktot) && (n0 + row < p.N)) ? 16 : 0;
      cpasync16(db + (uint32_t)(row * 36 + c4) * 4, g, sz);
    }
  };

  const int nkt = p.nkt;
#pragma unroll
  for (int s = 0; s < STAGES - 1; s++) {
    if (s < nkt) issue(s);
    CP_COMMIT();
  }

  for (int kt = 0; kt < nkt; kt++) {
    asm volatile("cp.async.wait_group %0;\n" :: "n"(STAGES - 2) : "memory");
    __syncthreads();
    if (kt + STAGES - 1 < nkt) issue(kt + STAGES - 1);
    CP_COMMIT();

    int buf = kt & (STAGES - 1);
    const uint32_t* a = (const uint32_t*)(As + (size_t)buf * ASZ);
    const uint32_t* b = (const uint32_t*)(Bs + (size_t)buf * BSZ);
#pragma unroll
    for (int ks = 0; ks < 4; ks++) {
      uint32_t af[4][4], bf[8][2];
      const int c = ks * 8 + tig;
#pragma unroll
      for (int tm = 0; tm < 4; tm++) {
        int r = wm * 64 + tm * 16 + gid;
        af[tm][0] = a[r * 36 + c];
        af[tm][1] = a[(r + 8) * 36 + c];
        af[tm][2] = a[r * 36 + c + 4];
        af[tm][3] = a[(r + 8) * 36 + c + 4];
      }
#pragma unroll
      for (int tn = 0; tn < 8; tn++) {
        int n = wn * 64 + tn * 8 + gid;
        bf[tn][0] = b[n * 36 + c];
        bf[tn][1] = b[n * 36 + c + 4];
      }
#pragma unroll
      for (int tm = 0; tm < 4; tm++)
#pragma unroll
        for (int tn = 0; tn < 8; tn++) {
          asm volatile(
              "mma.sync.aligned.m16n8k8.row.col.f32.tf32.tf32.f32 "
              "{%0,%1,%2,%3}, {%4,%5,%6,%7}, {%8,%9}, {%0,%1,%2,%3};\n"
              : "+f"(acc[tm][tn][0]), "+f"(acc[tm][tn][1]),
                "+f"(acc[tm][tn][2]), "+f"(acc[tm][tn][3])
              : "r"(af[tm][0]), "r"(af[tm][1]), "r"(af[tm][2]), "r"(af[tm][3]),
                "r"(bf[tn][0]), "r"(bf[tn][1]));
        }
    }
  }

  // ---- epilogue ----
  if (p.partial) {
    float* cbase = p.C1 + (size_t)z * p.partStride;
#pragma unroll
    for (int tm = 0; tm < 4; tm++) {
      int r0 = m0 + wm * 64 + tm * 16 + gid;
#pragma unroll
      for (int tn = 0; tn < 8; tn++) {
        int c0 = n0 + wn * 64 + tn * 8 + 2 * tig;
#pragma unroll
        for (int h = 0; h < 2; h++) {
          float2 v = make_float2(acc[tm][tn][h * 2], acc[tm][tn][h * 2 + 1]);
          *(float2*)(cbase + (size_t)(r0 + h * 8) * 128 + c0) = v;
        }
      }
    }
    return;
  }

#pragma unroll
  for (int tn = 0; tn < 8; tn++) {
    int c0 = n0 + wn * 64 + tn * 8 + 2 * tig;
    float b0 = p.bias1[c0], b1 = p.bias1[c0 + 1];
    if (p.bias2) { b0 += p.bias2[c0]; b1 += p.bias2[c0 + 1]; }
#pragma unroll
    for (int tm = 0; tm < 4; tm++) {
      int r0 = m0 + wm * 64 + tm * 16 + gid;
#pragma unroll
      for (int h = 0; h < 2; h++) {
        int r = r0 + h * 8;
        float vx = acc[tm][tn][h * 2] + b0;
        float vy = acc[tm][tn][h * 2 + 1] + b1;
        if (p.addC) {
          float2 ad = *(const float2*)(p.addC + (size_t)r * p.addld + c0);
          vx += ad.x; vy += ad.y;
        }
        if (p.act == 2) { vx = tanhf(vx); vy = tanhf(vy); }
        if (p.C1)
          *(float2*)(p.C1 + (size_t)r * p.ldc1 + c0) = make_float2(vx, vy);
        if (p.C2)
          *(float2*)(p.C2 + (size_t)r * p.ldc2 + c0) =
              make_float2(rna(vx), rna(vy));
      }
    }
  }
}

// ---------------- host side --------------------------------------------------
static void launch_gemm(const GP& p, int gx, int gy, int gz) {
  dim3 grid(gx, gy, gz);
  gemm_k<<<grid, NTHREADS, SMEM_BYTES>>>(p);
}

extern "C" void kernel_launch(void* const* d_in, const int* in_sizes, int n_in,
                              void* d_out, int out_size) {
  (void)in_sizes; (void)n_in; (void)out_size;
  const float* input  = (const float*)d_in[0];
  const float* hidden = (const float*)d_in[1];
  const float* prevh  = (const float*)d_in[2];
  const float* cell   = (const float*)d_in[3];
  const float* W_ch2  = (const float*)d_in[4];
  const float* b_ch2  = (const float*)d_in[5];
  const float* W_cm2  = (const float*)d_in[6];
  const float* b_cm2  = (const float*)d_in[7];
  const float* W_mo   = (const float*)d_in[8];
  const float* b_mo   = (const float*)d_in[9];
  const float* W_ci   = (const float*)d_in[10];
  const float* b_ci   = (const float*)d_in[11];
  const float* W_ch   = (const float*)d_in[12];
  const float* b_ch   = (const float*)d_in[13];
  const float* W_fc   = (const float*)d_in[14];
  const float* b_fc   = (const float*)d_in[15];
  const float* bias   = (const float*)d_in[16];

  float* out_p = (float*)d_out;                 // [4096,256]
  float* nh_p  = out_p + (size_t)4096 * 256;    // new_hidden
  float* nc_p  = nh_p + (size_t)4096 * 2048;    // new_cell
  float* nph_p = nc_p + (size_t)4096 * 2048;    // new_prev_hidden (= h_proj)

  float *concat_p, *Wch2_p, *Wcm2_p, *Wmo_p, *Wci_p, *Wch_p, *Wfc_p;
  float *nhr_p, *lcr_p, *midp_p, *midr_p;
  cudaGetSymbolAddress((void**)&concat_p, g_concat);
  cudaGetSymbolAddress((void**)&Wch2_p, g_Wch2);
  cudaGetSymbolAddress((void**)&Wcm2_p, g_Wcm2);
  cudaGetSymbolAddress((void**)&Wmo_p, g_Wmo);
  cudaGetSymbolAddress((void**)&Wci_p, g_Wci);
  cudaGetSymbolAddress((void**)&Wch_p, g_Wch);
  cudaGetSymbolAddress((void**)&Wfc_p, g_Wfc);
  cudaGetSymbolAddress((void**)&nhr_p, g_nhr);
  cudaGetSymbolAddress((void**)&lcr_p, g_lcr);
  cudaGetSymbolAddress((void**)&midp_p, g_midp);
  cudaGetSymbolAddress((void**)&midr_p, g_midr);

  cudaFuncSetAttribute(gemm_k, cudaFuncAttributeMaxDynamicSharedMemorySize,
                       SMEM_BYTES);

  // ---- preprocessing: round to tf32 (RNA) once -------------------------------
  auto r1 = [&](float* dst, const float* src, size_t n) {
    int n4 = (int)(n >> 2);
    rna1d<<<(n4 + 255) / 256, 256>>>(dst, src, n4);
  };
  r1(Wch2_p, W_ch2, (size_t)2048 * 7168);
  r1(Wcm2_p, W_cm2, (size_t)100 * 7168);
  r1(Wci_p, W_ci, (size_t)2048 * 1024);
  r1(Wch_p, W_ch, (size_t)2048 * 2048);
  r1(Wfc_p, W_fc, (size_t)2048 * 2048);
  rna2d<<<(256 * (112 / 4) + 255) / 256, 256>>>(Wmo_p, 112, W_mo, 100,
                                                256, 100, 112);
  // concat = [input | hidden | prev_hidden | cell], rounded
  {
    int tot;
    tot = 4096 * (1024 / 4);
    rna2d<<<(tot + 255) / 256, 256>>>(concat_p, 7168, input, 1024, 4096, 1024, 1024);
    tot = 4096 * (2048 / 4);
    rna2d<<<(tot + 255) / 256, 256>>>(concat_p + 1024, 7168, hidden, 2048, 4096, 2048, 2048);
    rna2d<<<(tot + 255) / 256, 256>>>(concat_p + 3072, 7168, prevh, 2048, 4096, 2048, 2048);
    rna2d<<<(tot + 255) / 256, 256>>>(concat_p + 5120, 7168, cell, 2048, 4096, 2048, 2048);
  }

  // 1) new_hidden = concat @ W_ch2^T + b_ch2   (exact -> nh_p, rounded -> g_nhr)
  {
    GP p{};
    p.M = 4096; p.N = 2048; p.Ktot = 7168; p.lda = 7168; p.ldb = 7168;
    p.A = concat_p; p.B = Wch2_p; p.bias1 = b_ch2;
    p.C1 = nh_p; p.ldc1 = 2048; p.C2 = nhr_p; p.ldc2 = 2048;
    p.nkt = 224;
    launch_gemm(p, 16, 16, 1);
  }
  // 2) mid partials = concat @ W_cm2^T  (split-K x8)
  {
    GP p{};
    p.M = 4096; p.N = 100; p.Ktot = 7168; p.lda = 7168; p.ldb = 7168;
    p.A = concat_p; p.B = Wcm2_p;
    p.C1 = midp_p; p.partial = 1; p.partStride = (long long)4096 * 128;
    p.nkt = 28;  // 28*32*8 = 7168
    launch_gemm(p, 1, 16, 8);
  }
  // 2b) mid = rna(relu(sum partials + b_cm2))
  reduce_mid<<<(4096 * 112 + 255) / 256, 256>>>(midp_p, b_cm2, midr_p);
  // 3) out = mid @ W_mo^T + b_mo
  {
    GP p{};
    p.M = 4096; p.N = 256; p.Ktot = 112; p.lda = 112; p.ldb = 112;
    p.A = midr_p; p.B = Wmo_p; p.bias1 = b_mo;
    p.C1 = out_p; p.ldc1 = 256;
    p.nkt = 4;
    launch_gemm(p, 2, 16, 1);
  }
  // 4) h_proj = new_hidden @ W_ch^T + b_ch  -> new_prev_hidden (exact)
  {
    GP p{};
    p.M = 4096; p.N = 2048; p.Ktot = 2048; p.lda = 2048; p.ldb = 2048;
    p.A = nhr_p; p.B = Wch_p; p.bias1 = b_ch;
    p.C1 = nph_p; p.ldc1 = 2048;
    p.nkt = 64;
    launch_gemm(p, 16, 16, 1);
  }
  // 5) lc = input @ W_ci^T + b_ci + bias + h_proj   (rounded -> g_lcr)
  {
    GP p{};
    p.M = 4096; p.N = 2048; p.Ktot = 1024; p.lda = 7168; p.ldb = 1024;
    p.A = concat_p;  // first 1024 cols = rounded input
    p.B = Wci_p; p.bias1 = b_ci; p.bias2 = bias;
    p.addC = nph_p; p.addld = 2048;
    p.C2 = lcr_p; p.ldc2 = 2048;
    p.nkt = 32;
    launch_gemm(p, 16, 16, 1);
  }
  // 6) new_cell = tanh(lc @ W_fc^T + b_fc)
  {
    GP p{};
    p.M = 4096; p.N = 2048; p.Ktot = 2048; p.lda = 2048; p.ldb = 2048;
    p.A = lcr_p; p.B = Wfc_p; p.bias1 = b_fc;
    p.C1 = nc_p; p.ldc1 = 2048; p.act = 2;
    p.nkt = 64;
    launch_gemm(p, 16, 16, 1);
  }
}